// round 11
// baseline (speedup 1.0000x reference)
#include <cuda_runtime.h>
#include <cuda_fp16.h>
#include <float.h>
#include <stdint.h>

#define B_ROWS 65536
#define K_CL   1024
#define D_DIM  256
#define LR_F   0.05f

#define TM     128        // CTA M tile
#define TN     128        // CTA N tile
#define NT     (K_CL / TN)   // 8 N-tiles
#define NCHUNK 8          // single fp16 pass: 8 chunks of K=32
#define ROWB   80         // padded smem row: 32 fp16 = 64B -> 80B (conflict-free LDSM)
#define ATILE  (TM * ROWB)          // 10240 B
#define SMEMD  (4 * ATILE)          // A0,A1,B0,B1 = 40960 B
#define RPC    64         // rows per phaseb CTA

// ---------------- device scratch ----------------
__device__ float   g_sumx[K_CL * D_DIM];   // per-cluster sum of x
__device__ int     g_cnt[K_CL];            // per-cluster row count
__device__ int     g_cur[K_CL];            // scatter cursor (prefix offsets)
__device__ int     g_order[B_ROWS];        // row ids sorted by cluster
__device__ float   g_c[K_CL];              // ||e_k||^2
__device__ int     g_nmin[B_ROWS];
__device__ double  g_commit;
__device__ double  g_som;
__device__ __half  g_xh[B_ROWS * D_DIM];
__device__ __half  g_eh[K_CL * D_DIM];
__device__ float4  g_cand[(size_t)B_ROWS * NT];   // top-2 per (row, tile)

// ---------------- helpers ----------------
__device__ __forceinline__ uint32_t smem_u32(const void* p) {
    uint32_t a;
    asm("{ .reg .u64 t; cvta.to.shared.u64 t, %1; cvt.u32.u64 %0, t; }" : "=r"(a) : "l"(p));
    return a;
}
__device__ __forceinline__ void ldsm4(uint32_t* r, uint32_t addr) {
    asm volatile("ldmatrix.sync.aligned.m8n8.x4.shared.b16 {%0,%1,%2,%3}, [%4];"
        : "=r"(r[0]), "=r"(r[1]), "=r"(r[2]), "=r"(r[3]) : "r"(addr));
}
__device__ __forceinline__ void mma_f16(float* c, const uint32_t* a, const uint32_t* b) {
    asm volatile("mma.sync.aligned.m16n8k16.row.col.f32.f16.f16.f32 "
        "{%0,%1,%2,%3}, {%4,%5,%6,%7}, {%8,%9}, {%0,%1,%2,%3};"
        : "+f"(c[0]), "+f"(c[1]), "+f"(c[2]), "+f"(c[3])
        : "r"(a[0]), "r"(a[1]), "r"(a[2]), "r"(a[3]), "r"(b[0]), "r"(b[1]));
}
__device__ __forceinline__ bool lessc(float a, int ka, float b, int kb) {
    return a < b || (a == b && ka < kb);
}
__device__ __forceinline__ void merge2(float& bv, int& bk, float& sv, int& sk,
                                       float v, int k) {
    if (lessc(v, k, bv, bk)) { sv = bv; sk = bk; bv = v; bk = k; }
    else if (lessc(v, k, sv, sk)) { sv = v; sk = k; }
}

// ---------------- prep: zero sumx/cnt, c[k]=||e_k||^2, e -> fp16 ----------------
__global__ void prep_kernel(const float* __restrict__ e) {
    int k = blockIdx.x, t = threadIdx.x;
    int idx = k * D_DIM + t;
    g_sumx[idx] = 0.0f;
    float v = e[idx];
    g_eh[idx] = __float2half_rn(v);
    float sq = v * v;
    #pragma unroll
    for (int off = 16; off > 0; off >>= 1)
        sq += __shfl_down_sync(0xffffffffu, sq, off);
    __shared__ float ws[8];
    int lane = t & 31, wid = t >> 5;
    if (lane == 0) ws[wid] = sq;
    __syncthreads();
    if (t == 0) {
        float s = 0.f;
        #pragma unroll
        for (int i = 0; i < 8; i++) s += sq = ws[i], s += 0.f;  // (placeholder avoided below)
    }
    if (t == 0) {
        float s = 0.f;
        #pragma unroll
        for (int i = 0; i < 8; i++) s += ws[i];
        g_c[k] = s;
        g_cnt[k] = 0;
        if (k == 0) { g_commit = 0.0; g_som = 0.0; }
    }
}

// ---------------- convert x to fp16 ----------------
__global__ void convx_kernel(const float* __restrict__ x) {
    int i = blockIdx.x * 256 + threadIdx.x;          // float4 index
    float4 v = ((const float4*)x)[i];
    __half2* xh2 = (__half2*)g_xh;
    xh2[i * 2]     = __halves2half2(__float2half_rn(v.x), __float2half_rn(v.y));
    xh2[i * 2 + 1] = __halves2half2(__float2half_rn(v.z), __float2half_rn(v.w));
}

// ---------------- mma.sync fp16 GEMM + top-2 argmin epilogue ----------------
// grid (NT, B_ROWS/TM) = (8, 512); 256 threads; warp grid 2(M) x 4(N), warp tile 64x32.
__global__ __launch_bounds__(256, 2) void gemm_argmin_kernel() {
    extern __shared__ __align__(128) char dsm[];
    __shared__ float cs[TN];

    const int tid = threadIdx.x;
    const int lane = tid & 31, wid = tid >> 5;
    const int wr = wid >> 2, wc = wid & 3;
    const int nt = blockIdx.x, n0 = nt * TN;
    const int m0 = blockIdx.y * TM;
    const uint32_t sb = smem_u32(dsm);

    if (tid < TN) cs[tid] = g_c[n0 + tid];

    const int srow = tid >> 2, sq = tid & 3;

    const uint32_t aoff = (uint32_t)((wr * 64 + (lane & 15)) * ROWB + (lane >> 4) * 16);
    const uint32_t boff = (uint32_t)((wc * 32 + (lane & 7) + ((lane & 16) ? 8 : 0)) * ROWB
                                     + ((lane & 8) ? 16 : 0));

    float c[4][4][4];
    #pragma unroll
    for (int mi = 0; mi < 4; mi++)
        #pragma unroll
        for (int g = 0; g < 4; g++)
            #pragma unroll
            for (int e2 = 0; e2 < 4; e2++) c[mi][g][e2] = 0.f;

    {
        #pragma unroll
        for (int i = 0; i < 2; i++) {
            int r = srow + i * 64;
            uint4 va = *(const uint4*)(g_xh + (size_t)(m0 + r) * D_DIM + sq * 8);
            *(uint4*)(dsm + r * ROWB + sq * 16) = va;
            uint4 vb = *(const uint4*)(g_eh + (size_t)(n0 + r) * D_DIM + sq * 8);
            *(uint4*)(dsm + 2 * ATILE + r * ROWB + sq * 16) = vb;
        }
    }
    __syncthreads();

    uint4 pa[2], pb[2];
    for (int ck = 0; ck < NCHUNK; ck++) {
        const int buf = ck & 1;

        if (ck < NCHUNK - 1) {
            const int d0 = (ck + 1) * 32;
            #pragma unroll
            for (int i = 0; i < 2; i++) {
                int r = srow + i * 64;
                pa[i] = *(const uint4*)(g_xh + (size_t)(m0 + r) * D_DIM + d0 + sq * 8);
                pb[i] = *(const uint4*)(g_eh + (size_t)(n0 + r) * D_DIM + d0 + sq * 8);
            }
        }

        const uint32_t aAdr = sb + buf * ATILE + aoff;
        const uint32_t bAdr = sb + 2 * ATILE + buf * ATILE + boff;
        #pragma unroll
        for (int kj = 0; kj < 2; kj++) {
            uint32_t af[4][4], bfr[2][4];
            #pragma unroll
            for (int mi = 0; mi < 4; mi++) ldsm4(af[mi], aAdr + mi * 16 * ROWB + kj * 32);
            #pragma unroll
            for (int gp = 0; gp < 2; gp++) ldsm4(bfr[gp], bAdr + gp * 16 * ROWB + kj * 32);
            #pragma unroll
            for (int mi = 0; mi < 4; mi++)
                #pragma unroll
                for (int g = 0; g < 4; g++)
                    mma_f16(c[mi][g], af[mi], &bfr[g >> 1][(g & 1) * 2]);
        }

        if (ck < NCHUNK - 1) {
            const int nb = (ck + 1) & 1;
            #pragma unroll
            for (int i = 0; i < 2; i++) {
                int r = srow + i * 64;
                *(uint4*)(dsm + nb * ATILE + r * ROWB + sq * 16) = pa[i];
                *(uint4*)(dsm + 2 * ATILE + nb * ATILE + r * ROWB + sq * 16) = pb[i];
            }
        }
        __syncthreads();
    }

    // ---- epilogue: per-row top-2 over this CTA's 128 cols ----
    float2* red = (float2*)dsm;

    #pragma unroll
    for (int mi = 0; mi < 4; mi++) {
        #pragma unroll
        for (int half = 0; half < 2; half++) {
            int rloc = wr * 64 + mi * 16 + (lane >> 2) + half * 8;
            float bv = FLT_MAX, sv = FLT_MAX;
            int bk = 0x7fffffff, sk = 0x7fffffff;
            #pragma unroll
            for (int g = 0; g < 4; g++) {
                #pragma unroll
                for (int e2 = 0; e2 < 2; e2++) {
                    int col = wc * 32 + g * 8 + (lane & 3) * 2 + e2;
                    float s = cs[col] - 2.0f * c[mi][g][half * 2 + e2];
                    merge2(bv, bk, sv, sk, s, n0 + col);
                }
            }
            #pragma unroll
            for (int off = 1; off <= 2; off <<= 1) {
                float obv = __shfl_xor_sync(0xffffffffu, bv, off);
                int   obk = __shfl_xor_sync(0xffffffffu, bk, off);
                float osv = __shfl_xor_sync(0xffffffffu, sv, off);
                int   osk = __shfl_xor_sync(0xffffffffu, sk, off);
                merge2(bv, bk, sv, sk, obv, obk);
                merge2(bv, bk, sv, sk, osv, osk);
            }
            if ((lane & 3) == 0) {
                red[(rloc * 4 + wc) * 2 + 0] = make_float2(bv, __int_as_float(bk));
                red[(rloc * 4 + wc) * 2 + 1] = make_float2(sv, __int_as_float(sk));
            }
        }
    }
    __syncthreads();

    if (tid < TM) {
        float bv = FLT_MAX, sv = FLT_MAX;
        int bk = 0x7fffffff, sk = 0x7fffffff;
        #pragma unroll
        for (int w = 0; w < 4; w++)
            #pragma unroll
            for (int p = 0; p < 2; p++) {
                float2 t = red[(tid * 4 + w) * 2 + p];
                merge2(bv, bk, sv, sk, t.x, __float_as_int(t.y));
            }
        g_cand[(size_t)(m0 + tid) * NT + nt] =
            make_float4(bv, __int_as_float(bk), sv, __int_as_float(sk));
    }
}

// ---------------- select: 8 lanes per row; near-ties rescored in EXACT fp32 ------------
#define MARGIN 0.05f
__global__ void select_kernel(const float* __restrict__ x, const float* __restrict__ e) {
    const int tid = threadIdx.x;
    const int l8 = tid & 7;
    const int b = blockIdx.x * 32 + (tid >> 3);

    float4 c0 = g_cand[(size_t)b * NT + l8];
    float v0 = c0.x; int k0 = __float_as_int(c0.y);
    float v1 = c0.z; int k1 = __float_as_int(c0.w);

    float bv = v0; int bk = k0;
    if (lessc(v1, k1, bv, bk)) { bv = v1; bk = k1; }
    #pragma unroll
    for (int off = 4; off > 0; off >>= 1) {
        float ov = __shfl_down_sync(0xffffffffu, bv, off, 8);
        int   ok = __shfl_down_sync(0xffffffffu, bk, off, 8);
        if (lessc(ov, ok, bv, bk)) { bv = ov; bk = ok; }
    }
    bv = __shfl_sync(0xffffffffu, bv, 0, 8);
    bk = __shfl_sync(0xffffffffu, bk, 0, 8);

    int cnt = (v0 <= bv + MARGIN ? 1 : 0) + (v1 <= bv + MARGIN ? 1 : 0);
    #pragma unroll
    for (int off = 4; off > 0; off >>= 1)
        cnt += __shfl_down_sync(0xffffffffu, cnt, off, 8);

    if (l8 == 0) {
        if (cnt > 1) {
            float bs = FLT_MAX; int bki = 0x7fffffff;
            const float* xr = x + (size_t)b * D_DIM;
            for (int t = 0; t < NT; t++) {
                float4 ct = g_cand[(size_t)b * NT + t];
                float vv[2] = {ct.x, ct.z};
                int   kv[2] = {__float_as_int(ct.y), __float_as_int(ct.w)};
                #pragma unroll
                for (int p = 0; p < 2; p++) {
                    if (vv[p] > bv + MARGIN) continue;
                    int k = kv[p];
                    float dot = 0.0f;
                    const float* er = e + (size_t)k * D_DIM;
                    #pragma unroll 8
                    for (int d = 0; d < D_DIM; d++) dot = fmaf(xr[d], er[d], dot);
                    float s = g_c[k] - 2.0f * dot;
                    if (s < bs || (s == bs && k < bki)) { bs = s; bki = k; }
                }
            }
            bk = bki;
        }
        g_nmin[b] = bk;
        atomicAdd(&g_cnt[bk], 1);
    }
}

// ---------------- prefix scan: g_cur[k] = exclusive prefix of g_cnt ----------------
__global__ void prefix_kernel() {
    __shared__ int s[K_CL];
    int t = threadIdx.x;           // 1024 threads
    int my = g_cnt[t];
    s[t] = my;
    __syncthreads();
    for (int off = 1; off < K_CL; off <<= 1) {
        int tmp = (t >= off) ? s[t - off] : 0;
        __syncthreads();
        s[t] += tmp;
        __syncthreads();
    }
    g_cur[t] = s[t] - my;          // exclusive
}

// ---------------- scatter rows by cluster ----------------
__global__ void scatter_kernel() {
    int b = blockIdx.x * 256 + threadIdx.x;
    int n = g_nmin[b];
    int pos = atomicAdd(&g_cur[n], 1);
    g_order[pos] = b;
}

// ---------------- phase B (sorted): z_q gather, losses, run-accumulated x-sums --------
// grid = B_ROWS/RPC = 1024 CTAs, 256 threads; thread t owns dim d = t.
__global__ __launch_bounds__(256) void phaseb_kernel(const float* __restrict__ x,
                                                     const float* __restrict__ e,
                                                     float* __restrict__ out) {
    const int d = threadIdx.x;
    const int base = blockIdx.x * RPC;

    float acc = 0.f;
    int cur = -1;
    float ev = 0.f, e0 = 0.f, e1 = 0.f, e2 = 0.f, e3 = 0.f;
    float commit = 0.f, som = 0.f;

    for (int i = 0; i < RPC; i++) {
        int b = g_order[base + i];
        int n = g_nmin[b];
        if (n != cur) {
            if (cur >= 0) atomicAdd(&g_sumx[cur * D_DIM + d], acc);
            acc = 0.f;
            cur = n;
            int nx = n >> 5, ny = n & 31;
            int iu  = (nx < 31 ? nx + 1 : nx) * 32 + ny;
            int idn = (nx > 0  ? nx - 1 : nx) * 32 + ny;
            int il  = nx * 32 + (ny > 0  ? ny - 1 : ny);
            int ir  = nx * 32 + (ny < 31 ? ny + 1 : ny);
            ev = e[n * D_DIM + d];
            e0 = e[iu * D_DIM + d];
            e1 = e[idn * D_DIM + d];
            e2 = e[il * D_DIM + d];
            e3 = e[ir * D_DIM + d];
        }
        float xv = x[(size_t)b * D_DIM + d];
        out[(size_t)b * D_DIM + d] = ev;
        float dw = xv - ev;
        commit = fmaf(dw, dw, commit);
        float a0 = xv - e0, a1 = xv - e1, a2 = xv - e2, a3 = xv - e3;
        som = fmaf(a0, a0, som); som = fmaf(a1, a1, som);
        som = fmaf(a2, a2, som); som = fmaf(a3, a3, som);
        acc += xv;
    }
    if (cur >= 0) atomicAdd(&g_sumx[cur * D_DIM + d], acc);

    // block-reduce losses
    #pragma unroll
    for (int off = 16; off > 0; off >>= 1) {
        commit += __shfl_down_sync(0xffffffffu, commit, off);
        som    += __shfl_down_sync(0xffffffffu, som, off);
    }
    __shared__ float wc_[8], ws_[8];
    int lane = d & 31, wid = d >> 5;
    if (lane == 0) { wc_[wid] = commit; ws_[wid] = som; }
    __syncthreads();
    if (d == 0) {
        float tc = 0.f, ts = 0.f;
        #pragma unroll
        for (int i = 0; i < 8; i++) { tc += wc_[i]; ts += ws_[i]; }
        atomicAdd(&g_commit, (double)tc);
        atomicAdd(&g_som, (double)ts);
    }
}

// ---------------- finalize: reconstruct all 5 segment terms from S ----------------
__global__ void finalize_kernel(const float* __restrict__ e, float* __restrict__ out) {
    const size_t OFF = (size_t)B_ROWS * D_DIM;
    int i = blockIdx.x * 256 + threadIdx.x;
    int k = i >> 8, d = i & 255;
    int kx = k >> 5, ky = k & 31;

    #define SVAL(j) (g_sumx[(j) * D_DIM + d] - (float)g_cnt[j] * e[(j) * D_DIM + d])

    float center = SVAL(k);
    float nbsum = 0.f;
    if (kx >= 1)  nbsum += SVAL(((kx - 1) << 5) | ky);
    if (kx == 31) nbsum += center;
    if (kx <= 30) nbsum += SVAL(((kx + 1) << 5) | ky);
    if (kx == 0)  nbsum += center;
    if (ky <= 30) nbsum += SVAL((kx << 5) | (ky + 1));
    if (ky == 0)  nbsum += center;
    if (ky >= 1)  nbsum += SVAL((kx << 5) | (ky - 1));
    if (ky == 31) nbsum += center;

    out[OFF + 2 + i] = e[i] + LR_F * center + 0.5f * LR_F * nbsum;
    if (i == 0) {
        out[OFF]     = (float)(g_commit / ((double)B_ROWS * (double)D_DIM));
        out[OFF + 1] = (float)(g_som / ((double)B_ROWS * 4.0 * (double)D_DIM));
    }
    #undef SVAL
}

// ---------------- launch ----------------
extern "C" void kernel_launch(void* const* d_in, const int* in_sizes, int n_in,
                              void* d_out, int out_size) {
    const float* x = (const float*)d_in[0];
    const float* e = (const float*)d_in[1];
    float* out = (float*)d_out;

    prep_kernel<<<K_CL, 256>>>(e);
    convx_kernel<<<B_ROWS * D_DIM / 4 / 256, 256>>>(x);
    dim3 ggrid(NT, B_ROWS / TM);
    gemm_argmin_kernel<<<ggrid, 256, SMEMD>>>();
    select_kernel<<<B_ROWS / 32, 256>>>(x, e);
    prefix_kernel<<<1, K_CL>>>();
    scatter_kernel<<<B_ROWS / 256, 256>>>();
    phaseb_kernel<<<B_ROWS / RPC, 256>>>(x, e, out);
    finalize_kernel<<<K_CL * D_DIM / 256, 256>>>(e, out);
}

// round 12
// speedup vs baseline: 1.1689x; 1.1689x over previous
#include <cuda_runtime.h>
#include <cuda_fp16.h>
#include <float.h>
#include <stdint.h>

#define B_ROWS 65536
#define K_CL   1024
#define D_DIM  256
#define LR_F   0.05f

#define TM     128        // CTA M tile
#define TN     128        // CTA N tile
#define NT     (K_CL / TN)   // 8 N-tiles
#define NCHUNK 8          // single fp16 pass: 8 chunks of K=32
#define ROWB   80         // padded smem row: 32 fp16 = 64B -> 80B (conflict-free LDSM)
#define ATILE  (TM * ROWB)          // 10240 B
#define SMEMD  (4 * ATILE)          // A0,A1,B0,B1 = 40960 B

// ---------------- device scratch ----------------
__device__ float   g_sumx[K_CL * D_DIM];   // per-cluster sum of x
__device__ int     g_cnt[K_CL];            // per-cluster row count
__device__ float   g_c[K_CL];              // ||e_k||^2
__device__ float   g_f[K_CL * D_DIM];      // sum of 4 neighbor e-rows
__device__ float   g_g[K_CL];              // sum of 4 neighbor ||e||^2
__device__ int     g_nmin[B_ROWS];
__device__ double  g_commit;
__device__ double  g_som;
__device__ __half  g_xh[B_ROWS * D_DIM];
__device__ __half  g_eh[K_CL * D_DIM];
__device__ float4  g_cand[(size_t)B_ROWS * NT];   // top-2 per (row, tile)

// ---------------- helpers ----------------
__device__ __forceinline__ uint32_t smem_u32(const void* p) {
    uint32_t a;
    asm("{ .reg .u64 t; cvta.to.shared.u64 t, %1; cvt.u32.u64 %0, t; }" : "=r"(a) : "l"(p));
    return a;
}
__device__ __forceinline__ void ldsm4(uint32_t* r, uint32_t addr) {
    asm volatile("ldmatrix.sync.aligned.m8n8.x4.shared.b16 {%0,%1,%2,%3}, [%4];"
        : "=r"(r[0]), "=r"(r[1]), "=r"(r[2]), "=r"(r[3]) : "r"(addr));
}
__device__ __forceinline__ void mma_f16(float* c, const uint32_t* a, const uint32_t* b) {
    asm volatile("mma.sync.aligned.m16n8k16.row.col.f32.f16.f16.f32 "
        "{%0,%1,%2,%3}, {%4,%5,%6,%7}, {%8,%9}, {%0,%1,%2,%3};"
        : "+f"(c[0]), "+f"(c[1]), "+f"(c[2]), "+f"(c[3])
        : "r"(a[0]), "r"(a[1]), "r"(a[2]), "r"(a[3]), "r"(b[0]), "r"(b[1]));
}
__device__ __forceinline__ bool lessc(float a, int ka, float b, int kb) {
    return a < b || (a == b && ka < kb);
}
__device__ __forceinline__ void merge2(float& bv, int& bk, float& sv, int& sk,
                                       float v, int k) {
    if (lessc(v, k, bv, bk)) { sv = bv; sk = bk; bv = v; bk = k; }
    else if (lessc(v, k, sv, sk)) { sv = v; sk = k; }
}
__device__ __forceinline__ void nbr4(int n, int* nb) {
    int nx = n >> 5, ny = n & 31;
    nb[0] = (nx < 31 ? nx + 1 : nx) * 32 + ny;   // up
    nb[1] = (nx > 0  ? nx - 1 : nx) * 32 + ny;   // down
    nb[2] = nx * 32 + (ny > 0  ? ny - 1 : ny);   // left
    nb[3] = nx * 32 + (ny < 31 ? ny + 1 : ny);   // right
}

// ---------------- prep: zero sumx/cnt, c[k]=||e_k||^2, e -> fp16, F vector ----------
__global__ void prep_kernel(const float* __restrict__ e) {
    int k = blockIdx.x, t = threadIdx.x;
    int idx = k * D_DIM + t;
    g_sumx[idx] = 0.0f;
    float v = e[idx];
    g_eh[idx] = __float2half_rn(v);

    int nb[4]; nbr4(k, nb);
    g_f[idx] = e[nb[0] * D_DIM + t] + e[nb[1] * D_DIM + t]
             + e[nb[2] * D_DIM + t] + e[nb[3] * D_DIM + t];

    float sq = v * v;
    #pragma unroll
    for (int off = 16; off > 0; off >>= 1)
        sq += __shfl_down_sync(0xffffffffu, sq, off);
    __shared__ float ws[8];
    int lane = t & 31, wid = t >> 5;
    if (lane == 0) ws[wid] = sq;
    __syncthreads();
    if (t == 0) {
        float s = 0.f;
        #pragma unroll
        for (int i = 0; i < 8; i++) s += ws[i];
        g_c[k] = s;
        g_cnt[k] = 0;
        if (k == 0) { g_commit = 0.0; g_som = 0.0; }
    }
}

// ---------------- convert x to fp16 ; block 0 computes G[k] ----------------
__global__ void convx_kernel(const float* __restrict__ x) {
    int i = blockIdx.x * 256 + threadIdx.x;          // float4 index
    float4 v = ((const float4*)x)[i];
    __half2* xh2 = (__half2*)g_xh;
    xh2[i * 2]     = __halves2half2(__float2half_rn(v.x), __float2half_rn(v.y));
    xh2[i * 2 + 1] = __halves2half2(__float2half_rn(v.z), __float2half_rn(v.w));

    if (blockIdx.x == 0) {
        #pragma unroll
        for (int j = 0; j < 4; j++) {
            int k = threadIdx.x * 4 + j;
            int nb[4]; nbr4(k, nb);
            g_g[k] = g_c[nb[0]] + g_c[nb[1]] + g_c[nb[2]] + g_c[nb[3]];
        }
    }
}

// ---------------- mma.sync fp16 GEMM + top-2 argmin epilogue ----------------
// grid (NT, B_ROWS/TM) = (8, 512); 256 threads; warp grid 2(M) x 4(N), warp tile 64x32.
__global__ __launch_bounds__(256, 2) void gemm_argmin_kernel() {
    extern __shared__ __align__(128) char dsm[];
    __shared__ float cs[TN];

    const int tid = threadIdx.x;
    const int lane = tid & 31, wid = tid >> 5;
    const int wr = wid >> 2, wc = wid & 3;
    const int nt = blockIdx.x, n0 = nt * TN;
    const int m0 = blockIdx.y * TM;
    const uint32_t sb = smem_u32(dsm);

    if (tid < TN) cs[tid] = g_c[n0 + tid];

    const int srow = tid >> 2, sq = tid & 3;

    const uint32_t aoff = (uint32_t)((wr * 64 + (lane & 15)) * ROWB + (lane >> 4) * 16);
    const uint32_t boff = (uint32_t)((wc * 32 + (lane & 7) + ((lane & 16) ? 8 : 0)) * ROWB
                                     + ((lane & 8) ? 16 : 0));

    float c[4][4][4];
    #pragma unroll
    for (int mi = 0; mi < 4; mi++)
        #pragma unroll
        for (int g = 0; g < 4; g++)
            #pragma unroll
            for (int e2 = 0; e2 < 4; e2++) c[mi][g][e2] = 0.f;

    {
        #pragma unroll
        for (int i = 0; i < 2; i++) {
            int r = srow + i * 64;
            uint4 va = *(const uint4*)(g_xh + (size_t)(m0 + r) * D_DIM + sq * 8);
            *(uint4*)(dsm + r * ROWB + sq * 16) = va;
            uint4 vb = *(const uint4*)(g_eh + (size_t)(n0 + r) * D_DIM + sq * 8);
            *(uint4*)(dsm + 2 * ATILE + r * ROWB + sq * 16) = vb;
        }
    }
    __syncthreads();

    uint4 pa[2], pb[2];
    for (int ck = 0; ck < NCHUNK; ck++) {
        const int buf = ck & 1;

        if (ck < NCHUNK - 1) {
            const int d0 = (ck + 1) * 32;
            #pragma unroll
            for (int i = 0; i < 2; i++) {
                int r = srow + i * 64;
                pa[i] = *(const uint4*)(g_xh + (size_t)(m0 + r) * D_DIM + d0 + sq * 8);
                pb[i] = *(const uint4*)(g_eh + (size_t)(n0 + r) * D_DIM + d0 + sq * 8);
            }
        }

        const uint32_t aAdr = sb + buf * ATILE + aoff;
        const uint32_t bAdr = sb + 2 * ATILE + buf * ATILE + boff;
        #pragma unroll
        for (int kj = 0; kj < 2; kj++) {
            uint32_t af[4][4], bfr[2][4];
            #pragma unroll
            for (int mi = 0; mi < 4; mi++) ldsm4(af[mi], aAdr + mi * 16 * ROWB + kj * 32);
            #pragma unroll
            for (int gp = 0; gp < 2; gp++) ldsm4(bfr[gp], bAdr + gp * 16 * ROWB + kj * 32);
            #pragma unroll
            for (int mi = 0; mi < 4; mi++)
                #pragma unroll
                for (int g = 0; g < 4; g++)
                    mma_f16(c[mi][g], af[mi], &bfr[g >> 1][(g & 1) * 2]);
        }

        if (ck < NCHUNK - 1) {
            const int nb = (ck + 1) & 1;
            #pragma unroll
            for (int i = 0; i < 2; i++) {
                int r = srow + i * 64;
                *(uint4*)(dsm + nb * ATILE + r * ROWB + sq * 16) = pa[i];
                *(uint4*)(dsm + 2 * ATILE + nb * ATILE + r * ROWB + sq * 16) = pb[i];
            }
        }
        __syncthreads();
    }

    // ---- epilogue: per-row top-2 over this CTA's 128 cols ----
    float2* red = (float2*)dsm;

    #pragma unroll
    for (int mi = 0; mi < 4; mi++) {
        #pragma unroll
        for (int half = 0; half < 2; half++) {
            int rloc = wr * 64 + mi * 16 + (lane >> 2) + half * 8;
            float bv = FLT_MAX, sv = FLT_MAX;
            int bk = 0x7fffffff, sk = 0x7fffffff;
            #pragma unroll
            for (int g = 0; g < 4; g++) {
                #pragma unroll
                for (int e2 = 0; e2 < 2; e2++) {
                    int col = wc * 32 + g * 8 + (lane & 3) * 2 + e2;
                    float s = cs[col] - 2.0f * c[mi][g][half * 2 + e2];
                    merge2(bv, bk, sv, sk, s, n0 + col);
                }
            }
            #pragma unroll
            for (int off = 1; off <= 2; off <<= 1) {
                float obv = __shfl_xor_sync(0xffffffffu, bv, off);
                int   obk = __shfl_xor_sync(0xffffffffu, bk, off);
                float osv = __shfl_xor_sync(0xffffffffu, sv, off);
                int   osk = __shfl_xor_sync(0xffffffffu, sk, off);
                merge2(bv, bk, sv, sk, obv, obk);
                merge2(bv, bk, sv, sk, osv, osk);
            }
            if ((lane & 3) == 0) {
                red[(rloc * 4 + wc) * 2 + 0] = make_float2(bv, __int_as_float(bk));
                red[(rloc * 4 + wc) * 2 + 1] = make_float2(sv, __int_as_float(sk));
            }
        }
    }
    __syncthreads();

    if (tid < TM) {
        float bv = FLT_MAX, sv = FLT_MAX;
        int bk = 0x7fffffff, sk = 0x7fffffff;
        #pragma unroll
        for (int w = 0; w < 4; w++)
            #pragma unroll
            for (int p = 0; p < 2; p++) {
                float2 t = red[(tid * 4 + w) * 2 + p];
                merge2(bv, bk, sv, sk, t.x, __float_as_int(t.y));
            }
        g_cand[(size_t)(m0 + tid) * NT + nt] =
            make_float4(bv, __int_as_float(bk), sv, __int_as_float(sk));
    }
}

// ---------------- select: 8 lanes per row; rescue parallel across lanes ---------------
// Rescore arithmetic per (b,k) bit-matches the known-passing full-fp32 kernel:
// dot = sequential fmaf chain; score = g_c[k] - 2*dot; lowest (tie -> lowest k).
#define MARGIN 0.05f
__global__ void select_kernel(const float* __restrict__ x, const float* __restrict__ e) {
    const int tid = threadIdx.x;
    const int l8 = tid & 7;
    const int b = blockIdx.x * 32 + (tid >> 3);

    float4 c0 = g_cand[(size_t)b * NT + l8];
    float v0 = c0.x; int k0 = __float_as_int(c0.y);
    float v1 = c0.z; int k1 = __float_as_int(c0.w);

    float bv = v0; int bk = k0;
    if (lessc(v1, k1, bv, bk)) { bv = v1; bk = k1; }
    // full butterfly min over 8-lane group (everyone gets result)
    #pragma unroll
    for (int off = 1; off < 8; off <<= 1) {
        float ov = __shfl_xor_sync(0xffffffffu, bv, off);
        int   ok = __shfl_xor_sync(0xffffffffu, bk, off);
        if (lessc(ov, ok, bv, bk)) { bv = ov; bk = ok; }
    }

    // candidate count within margin (butterfly -> everyone)
    int cnt = (v0 <= bv + MARGIN ? 1 : 0) + (v1 <= bv + MARGIN ? 1 : 0);
    #pragma unroll
    for (int off = 1; off < 8; off <<= 1)
        cnt += __shfl_xor_sync(0xffffffffu, cnt, off);

    if (cnt > 1) {
        // parallel exact fp32 rescore: each lane handles its own tile's candidates
        float bs = FLT_MAX; int bki = 0x7fffffff;
        const float* xr = x + (size_t)b * D_DIM;
        float vv[2] = {v0, v1};
        int   kv[2] = {k0, k1};
        #pragma unroll
        for (int p = 0; p < 2; p++) {
            if (vv[p] > bv + MARGIN) continue;
            int k = kv[p];
            float dot = 0.0f;
            const float* er = e + (size_t)k * D_DIM;
            #pragma unroll 8
            for (int d = 0; d < D_DIM; d++) dot = fmaf(xr[d], er[d], dot);
            float s = g_c[k] - 2.0f * dot;
            if (lessc(s, k, bs, bki)) { bs = s; bki = k; }
        }
        #pragma unroll
        for (int off = 1; off < 8; off <<= 1) {
            float os = __shfl_xor_sync(0xffffffffu, bs, off);
            int   ok = __shfl_xor_sync(0xffffffffu, bki, off);
            if (lessc(os, ok, bs, bki)) { bs = os; bki = ok; }
        }
        bk = bki;
    }
    if (l8 == 0) {
        g_nmin[b] = bk;
        atomicAdd(&g_cnt[bk], 1);
    }
}

// ---------------- phase B: z_q gather, losses (F/G form), x-sum atomics --------------
__global__ void phaseb_kernel(const float* __restrict__ x, const float* __restrict__ e,
                              float* __restrict__ out) {
    const int warp = threadIdx.x >> 5;
    const int lane = threadIdx.x & 31;
    const int b = blockIdx.x * 8 + warp;

    int n = g_nmin[b];

    const float4* xr = (const float4*)(x + (size_t)b * D_DIM);
    const float4* zr = (const float4*)(e + (size_t)n * D_DIM);
    const float4* fr = (const float4*)(g_f + (size_t)n * D_DIM);
    float4* zout = (float4*)out + (size_t)b * (D_DIM / 4);

    float commit = 0.f, som = 0.f;

    #pragma unroll
    for (int it = 0; it < 2; it++) {
        int q = lane + it * 32;
        float4 xv = xr[q];
        float4 zq = zr[q];
        float4 fv = fr[q];
        zout[q] = zq;
        float4 dw = make_float4(xv.x - zq.x, xv.y - zq.y, xv.z - zq.z, xv.w - zq.w);
        commit += dw.x * dw.x + dw.y * dw.y + dw.z * dw.z + dw.w * dw.w;

        float xx = xv.x * xv.x + xv.y * xv.y + xv.z * xv.z + xv.w * xv.w;
        float xf = xv.x * fv.x + xv.y * fv.y + xv.z * fv.z + xv.w * fv.w;
        som += 4.0f * xx - 2.0f * xf;

        int base = n * D_DIM + q * 4;
        atomicAdd(&g_sumx[base + 0], xv.x);
        atomicAdd(&g_sumx[base + 1], xv.y);
        atomicAdd(&g_sumx[base + 2], xv.z);
        atomicAdd(&g_sumx[base + 3], xv.w);
    }

    #pragma unroll
    for (int off = 16; off > 0; off >>= 1) {
        commit += __shfl_down_sync(0xffffffffu, commit, off);
        som    += __shfl_down_sync(0xffffffffu, som, off);
    }
    if (lane == 0) {
        som += g_g[n];
        atomicAdd(&g_commit, (double)commit);
        atomicAdd(&g_som, (double)som);
    }
}

// ---------------- finalize: reconstruct all 5 segment terms from S ----------------
__global__ void finalize_kernel(const float* __restrict__ e, float* __restrict__ out) {
    const size_t OFF = (size_t)B_ROWS * D_DIM;
    int i = blockIdx.x * 256 + threadIdx.x;
    int k = i >> 8, d = i & 255;
    int kx = k >> 5, ky = k & 31;

    #define SVAL(j) (g_sumx[(j) * D_DIM + d] - (float)g_cnt[j] * e[(j) * D_DIM + d])

    float center = SVAL(k);
    float nbsum = 0.f;
    if (kx >= 1)  nbsum += SVAL(((kx - 1) << 5) | ky);
    if (kx == 31) nbsum += center;
    if (kx <= 30) nbsum += SVAL(((kx + 1) << 5) | ky);
    if (kx == 0)  nbsum += center;
    if (ky <= 30) nbsum += SVAL((kx << 5) | (ky + 1));
    if (ky == 0)  nbsum += center;
    if (ky >= 1)  nbsum += SVAL((kx << 5) | (ky - 1));
    if (ky == 31) nbsum += center;

    out[OFF + 2 + i] = e[i] + LR_F * center + 0.5f * LR_F * nbsum;
    if (i == 0) {
        out[OFF]     = (float)(g_commit / ((double)B_ROWS * (double)D_DIM));
        out[OFF + 1] = (float)(g_som / ((double)B_ROWS * 4.0 * (double)D_DIM));
    }
    #undef SVAL
}

// ---------------- launch ----------------
extern "C" void kernel_launch(void* const* d_in, const int* in_sizes, int n_in,
                              void* d_out, int out_size) {
    const float* x = (const float*)d_in[0];
    const float* e = (const float*)d_in[1];
    float* out = (float*)d_out;

    prep_kernel<<<K_CL, 256>>>(e);
    convx_kernel<<<B_ROWS * D_DIM / 4 / 256, 256>>>(x);
    dim3 ggrid(NT, B_ROWS / TM);
    gemm_argmin_kernel<<<ggrid, 256, SMEMD>>>();
    select_kernel<<<B_ROWS / 32, 256>>>(x, e);
    phaseb_kernel<<<B_ROWS / 8, 256>>>(x, e, out);
    finalize_kernel<<<K_CL * D_DIM / 256, 256>>>(e, out);
}

// round 14
// speedup vs baseline: 1.3386x; 1.1452x over previous
#include <cuda_runtime.h>
#include <cuda_fp16.h>
#include <float.h>
#include <stdint.h>

#define B_ROWS 65536
#define K_CL   1024
#define D_DIM  256
#define LR_F   0.05f

#define TM     128        // CTA M tile
#define TN     128        // CTA N tile
#define NT     (K_CL / TN)   // 8 N-tiles
#define KC     64         // K per chunk (halfs)
#define NCHUNK (D_DIM / KC)  // 4
#define ROWB   144        // 64 halfs = 128B payload -> 144B padded row (16B aligned)
#define ATILE  (TM * ROWB)          // 18432 B
#define SMEMD  (4 * ATILE)          // A0,A1,B0,B1 = 73728 B

// ---------------- device scratch ----------------
__device__ __align__(16) float g_sumx[K_CL * D_DIM];   // per-cluster sum of x
__device__ int     g_cnt[K_CL];            // per-cluster row count
__device__ float   g_c[K_CL];              // ||e_k||^2
__device__ __align__(16) float g_f[K_CL * D_DIM];      // sum of 4 neighbor e-rows
__device__ float   g_g[K_CL];              // sum of 4 neighbor ||e||^2
__device__ int     g_nmin[B_ROWS];
__device__ double  g_commit;
__device__ double  g_som;
__device__ __half  g_xh[B_ROWS * D_DIM];
__device__ __half  g_eh[K_CL * D_DIM];
__device__ float4  g_cand[(size_t)B_ROWS * NT];   // top-2 per (row, tile)

// ---------------- helpers ----------------
__device__ __forceinline__ uint32_t smem_u32(const void* p) {
    uint32_t a;
    asm("{ .reg .u64 t; cvta.to.shared.u64 t, %1; cvt.u32.u64 %0, t; }" : "=r"(a) : "l"(p));
    return a;
}
__device__ __forceinline__ void ldsm4(uint32_t* r, uint32_t addr) {
    asm volatile("ldmatrix.sync.aligned.m8n8.x4.shared.b16 {%0,%1,%2,%3}, [%4];"
        : "=r"(r[0]), "=r"(r[1]), "=r"(r[2]), "=r"(r[3]) : "r"(addr));
}
__device__ __forceinline__ void mma_f16(float* c, const uint32_t* a, const uint32_t* b) {
    asm volatile("mma.sync.aligned.m16n8k16.row.col.f32.f16.f16.f32 "
        "{%0,%1,%2,%3}, {%4,%5,%6,%7}, {%8,%9}, {%0,%1,%2,%3};"
        : "+f"(c[0]), "+f"(c[1]), "+f"(c[2]), "+f"(c[3])
        : "r"(a[0]), "r"(a[1]), "r"(a[2]), "r"(a[3]), "r"(b[0]), "r"(b[1]));
}
#define CP_ASYNC16(dst, src) \
    asm volatile("cp.async.cg.shared.global [%0], [%1], 16;" :: "r"(dst), "l"(src))
#define CP_COMMIT()  asm volatile("cp.async.commit_group;" ::: "memory")
#define CP_WAIT(n)   asm volatile("cp.async.wait_group %0;" :: "n"(n) : "memory")

__device__ __forceinline__ void red_v4(float* ptr, float a, float b, float c, float d) {
    asm volatile("{ .reg .u64 p; cvta.to.global.u64 p, %0;\n\t"
                 "red.global.add.v4.f32 [p], {%1, %2, %3, %4}; }"
                 :: "l"(ptr), "f"(a), "f"(b), "f"(c), "f"(d) : "memory");
}
__device__ __forceinline__ bool lessc(float a, int ka, float b, int kb) {
    return a < b || (a == b && ka < kb);
}
__device__ __forceinline__ void merge2(float& bv, int& bk, float& sv, int& sk,
                                       float v, int k) {
    if (lessc(v, k, bv, bk)) { sv = bv; sk = bk; bv = v; bk = k; }
    else if (lessc(v, k, sv, sk)) { sv = v; sk = k; }
}
__device__ __forceinline__ void nbr4(int n, int* nb) {
    int nx = n >> 5, ny = n & 31;
    nb[0] = (nx < 31 ? nx + 1 : nx) * 32 + ny;   // up
    nb[1] = (nx > 0  ? nx - 1 : nx) * 32 + ny;   // down
    nb[2] = nx * 32 + (ny > 0  ? ny - 1 : ny);   // left
    nb[3] = nx * 32 + (ny < 31 ? ny + 1 : ny);   // right
}

// ---------------- prep: zero sumx/cnt, c[k]=||e_k||^2, e -> fp16, F vector ----------
__global__ void prep_kernel(const float* __restrict__ e) {
    int k = blockIdx.x, t = threadIdx.x;
    int idx = k * D_DIM + t;
    g_sumx[idx] = 0.0f;
    float v = e[idx];
    g_eh[idx] = __float2half_rn(v);

    int nb[4]; nbr4(k, nb);
    g_f[idx] = e[nb[0] * D_DIM + t] + e[nb[1] * D_DIM + t]
             + e[nb[2] * D_DIM + t] + e[nb[3] * D_DIM + t];

    float sq = v * v;
    #pragma unroll
    for (int off = 16; off > 0; off >>= 1)
        sq += __shfl_down_sync(0xffffffffu, sq, off);
    __shared__ float ws[8];
    int lane = t & 31, wid = t >> 5;
    if (lane == 0) ws[wid] = sq;
    __syncthreads();
    if (t == 0) {
        float s = 0.f;
        #pragma unroll
        for (int i = 0; i < 8; i++) s += ws[i];
        g_c[k] = s;
        g_cnt[k] = 0;
        if (k == 0) { g_commit = 0.0; g_som = 0.0; }
    }
}

// ---------------- convert x to fp16 ; block 0 computes G[k] ----------------
__global__ void convx_kernel(const float* __restrict__ x) {
    int i = blockIdx.x * 256 + threadIdx.x;          // float4 index
    float4 v = ((const float4*)x)[i];
    __half2* xh2 = (__half2*)g_xh;
    xh2[i * 2]     = __halves2half2(__float2half_rn(v.x), __float2half_rn(v.y));
    xh2[i * 2 + 1] = __halves2half2(__float2half_rn(v.z), __float2half_rn(v.w));

    if (blockIdx.x == 0) {
        #pragma unroll
        for (int j = 0; j < 4; j++) {
            int k = threadIdx.x * 4 + j;
            int nb[4]; nbr4(k, nb);
            g_g[k] = g_c[nb[0]] + g_c[nb[1]] + g_c[nb[2]] + g_c[nb[3]];
        }
    }
}

// ---------------- mma.sync fp16 GEMM (cp.async staged) + top-2 argmin epilogue -------
// grid (NT, B_ROWS/TM) = (8, 512); 256 threads; warp grid 2(M) x 4(N), warp tile 64x32.
// Staging per chunk: 128 rows x 128B per tile = 1024 x 16B; 4 cp.async per thread/tile.
__global__ __launch_bounds__(256, 2) void gemm_argmin_kernel() {
    extern __shared__ __align__(128) char dsm[];
    __shared__ float cs[TN];

    const int tid = threadIdx.x;
    const int lane = tid & 31, wid = tid >> 5;
    const int wr = wid >> 2, wc = wid & 3;
    const int nt = blockIdx.x, n0 = nt * TN;
    const int m0 = blockIdx.y * TM;
    const uint32_t sb = smem_u32(dsm);

    if (tid < TN) cs[tid] = g_c[n0 + tid];

    const uint32_t aoff = (uint32_t)((wr * 64 + (lane & 15)) * ROWB + (lane >> 4) * 16);
    const uint32_t boff = (uint32_t)((wc * 32 + (lane & 7) + ((lane & 16) ? 8 : 0)) * ROWB
                                     + ((lane & 8) ? 16 : 0));

    float c[4][4][4];
    #pragma unroll
    for (int mi = 0; mi < 4; mi++)
        #pragma unroll
        for (int g = 0; g < 4; g++)
            #pragma unroll
            for (int e2 = 0; e2 < 4; e2++) c[mi][g][e2] = 0.f;

    // prologue: stage chunk 0 into buf 0
    {
        #pragma unroll
        for (int i = 0; i < 4; i++) {
            int idx = i * 256 + tid;
            int row = idx >> 3, q = idx & 7;
            uint32_t so = (uint32_t)(row * ROWB + q * 16);
            CP_ASYNC16(sb + so, g_xh + (size_t)(m0 + row) * D_DIM + q * 8);
            CP_ASYNC16(sb + 2 * ATILE + so, g_eh + (size_t)(n0 + row) * D_DIM + q * 8);
        }
        CP_COMMIT();
    }

    for (int ck = 0; ck < NCHUNK; ck++) {
        const int buf = ck & 1;

        if (ck < NCHUNK - 1) {
            const int nb = (ck + 1) & 1;
            const int d0 = (ck + 1) * KC;
            #pragma unroll
            for (int i = 0; i < 4; i++) {
                int idx = i * 256 + tid;
                int row = idx >> 3, q = idx & 7;
                uint32_t so = (uint32_t)(nb * ATILE + row * ROWB + q * 16);
                CP_ASYNC16(sb + so, g_xh + (size_t)(m0 + row) * D_DIM + d0 + q * 8);
                CP_ASYNC16(sb + 2 * ATILE + so,
                           g_eh + (size_t)(n0 + row) * D_DIM + d0 + q * 8);
            }
            CP_COMMIT();
            CP_WAIT(1);          // chunk ck resident (newest group still in flight)
        } else {
            CP_WAIT(0);          // final chunk resident
        }
        __syncthreads();

        const uint32_t aAdr = sb + buf * ATILE + aoff;
        const uint32_t bAdr = sb + 2 * ATILE + buf * ATILE + boff;
        #pragma unroll
        for (int kj = 0; kj < 4; kj++) {        // 4 x K16 per K64 chunk
            uint32_t af[4][4], bfr[2][4];
            #pragma unroll
            for (int mi = 0; mi < 4; mi++) ldsm4(af[mi], aAdr + mi * 16 * ROWB + kj * 32);
            #pragma unroll
            for (int gp = 0; gp < 2; gp++) ldsm4(bfr[gp], bAdr + gp * 16 * ROWB + kj * 32);
            #pragma unroll
            for (int mi = 0; mi < 4; mi++)
                #pragma unroll
                for (int g = 0; g < 4; g++)
                    mma_f16(c[mi][g], af[mi], &bfr[g >> 1][(g & 1) * 2]);
        }
        __syncthreads();
    }

    // ---- epilogue: per-row top-2 over this CTA's 128 cols ----
    float2* red = (float2*)dsm;

    #pragma unroll
    for (int mi = 0; mi < 4; mi++) {
        #pragma unroll
        for (int half = 0; half < 2; half++) {
            int rloc = wr * 64 + mi * 16 + (lane >> 2) + half * 8;
            float bv = FLT_MAX, sv = FLT_MAX;
            int bk = 0x7fffffff, sk = 0x7fffffff;
            #pragma unroll
            for (int g = 0; g < 4; g++) {
                #pragma unroll
                for (int e2 = 0; e2 < 2; e2++) {
                    int col = wc * 32 + g * 8 + (lane & 3) * 2 + e2;
                    float s = cs[col] - 2.0f * c[mi][g][half * 2 + e2];
                    merge2(bv, bk, sv, sk, s, n0 + col);
                }
            }
            #pragma unroll
            for (int off = 1; off <= 2; off <<= 1) {
                float obv = __shfl_xor_sync(0xffffffffu, bv, off);
                int   obk = __shfl_xor_sync(0xffffffffu, bk, off);
                float osv = __shfl_xor_sync(0xffffffffu, sv, off);
                int   osk = __shfl_xor_sync(0xffffffffu, sk, off);
                merge2(bv, bk, sv, sk, obv, obk);
                merge2(bv, bk, sv, sk, osv, osk);
            }
            if ((lane & 3) == 0) {
                red[(rloc * 4 + wc) * 2 + 0] = make_float2(bv, __int_as_float(bk));
                red[(rloc * 4 + wc) * 2 + 1] = make_float2(sv, __int_as_float(sk));
            }
        }
    }
    __syncthreads();

    if (tid < TM) {
        float bv = FLT_MAX, sv = FLT_MAX;
        int bk = 0x7fffffff, sk = 0x7fffffff;
        #pragma unroll
        for (int w = 0; w < 4; w++)
            #pragma unroll
            for (int p = 0; p < 2; p++) {
                float2 t = red[(tid * 4 + w) * 2 + p];
                merge2(bv, bk, sv, sk, t.x, __float_as_int(t.y));
            }
        g_cand[(size_t)(m0 + tid) * NT + nt] =
            make_float4(bv, __int_as_float(bk), sv, __int_as_float(sk));
    }
}

// ---------------- select: 8 lanes per row; rescue parallel across lanes ---------------
// Rescore arithmetic per (b,k) bit-matches the known-passing full-fp32 kernel.
#define MARGIN 0.05f
__global__ void select_kernel(const float* __restrict__ x, const float* __restrict__ e) {
    const int tid = threadIdx.x;
    const int l8 = tid & 7;
    const int b = blockIdx.x * 32 + (tid >> 3);

    float4 c0 = g_cand[(size_t)b * NT + l8];
    float v0 = c0.x; int k0 = __float_as_int(c0.y);
    float v1 = c0.z; int k1 = __float_as_int(c0.w);

    float bv = v0; int bk = k0;
    if (lessc(v1, k1, bv, bk)) { bv = v1; bk = k1; }
    #pragma unroll
    for (int off = 1; off < 8; off <<= 1) {
        float ov = __shfl_xor_sync(0xffffffffu, bv, off);
        int   ok = __shfl_xor_sync(0xffffffffu, bk, off);
        if (lessc(ov, ok, bv, bk)) { bv = ov; bk = ok; }
    }

    int cnt = (v0 <= bv + MARGIN ? 1 : 0) + (v1 <= bv + MARGIN ? 1 : 0);
    #pragma unroll
    for (int off = 1; off < 8; off <<= 1)
        cnt += __shfl_xor_sync(0xffffffffu, cnt, off);

    if (cnt > 1) {
        float bs = FLT_MAX; int bki = 0x7fffffff;
        const float* xr = x + (size_t)b * D_DIM;
        float vv[2] = {v0, v1};
        int   kv[2] = {k0, k1};
        #pragma unroll
        for (int p = 0; p < 2; p++) {
            if (vv[p] > bv + MARGIN) continue;
            int k = kv[p];
            if ((unsigned)k >= (unsigned)K_CL) continue;   // sentinel guard
            float dot = 0.0f;
            const float* er = e + (size_t)k * D_DIM;
            #pragma unroll 8
            for (int d = 0; d < D_DIM; d++) dot = fmaf(xr[d], er[d], dot);
            float s = g_c[k] - 2.0f * dot;
            if (lessc(s, k, bs, bki)) { bs = s; bki = k; }
        }
        #pragma unroll
        for (int off = 1; off < 8; off <<= 1) {
            float os = __shfl_xor_sync(0xffffffffu, bs, off);
            int   ok = __shfl_xor_sync(0xffffffffu, bki, off);
            if (lessc(os, ok, bs, bki)) { bs = os; bki = ok; }
        }
        if ((unsigned)bki < (unsigned)K_CL) bk = bki;
    }
    if (l8 == 0) {
        g_nmin[b] = bk;
        atomicAdd(&g_cnt[bk], 1);
    }
}

// ---------------- phase B: z_q gather, losses (F/G form), v4-red x-sums --------------
__global__ void phaseb_kernel(const float* __restrict__ x, const float* __restrict__ e,
                              float* __restrict__ out) {
    const int warp = threadIdx.x >> 5;
    const int lane = threadIdx.x & 31;
    const int b = blockIdx.x * 8 + warp;

    int n = g_nmin[b];

    const float4* xr = (const float4*)(x + (size_t)b * D_DIM);
    const float4* zr = (const float4*)(e + (size_t)n * D_DIM);
    const float4* fr = (const float4*)(g_f + (size_t)n * D_DIM);
    float4* zout = (float4*)out + (size_t)b * (D_DIM / 4);

    float commit = 0.f, som = 0.f;

    #pragma unroll
    for (int it = 0; it < 2; it++) {
        int q = lane + it * 32;
        float4 xv = xr[q];
        float4 zq = zr[q];
        float4 fv = fr[q];
        zout[q] = zq;
        float4 dw = make_float4(xv.x - zq.x, xv.y - zq.y, xv.z - zq.z, xv.w - zq.w);
        commit += dw.x * dw.x + dw.y * dw.y + dw.z * dw.z + dw.w * dw.w;

        float xx = xv.x * xv.x + xv.y * xv.y + xv.z * xv.z + xv.w * xv.w;
        float xf = xv.x * fv.x + xv.y * fv.y + xv.z * fv.z + xv.w * fv.w;
        som += 4.0f * xx - 2.0f * xf;

        red_v4(&g_sumx[n * D_DIM + q * 4], xv.x, xv.y, xv.z, xv.w);
    }

    #pragma unroll
    for (int off = 16; off > 0; off >>= 1) {
        commit += __shfl_down_sync(0xffffffffu, commit, off);
        som    += __shfl_down_sync(0xffffffffu, som, off);
    }
    if (lane == 0) {
        som += g_g[n];
        atomicAdd(&g_commit, (double)commit);
        atomicAdd(&g_som, (double)som);
    }
}

// ---------------- finalize: reconstruct all 5 segment terms from S ----------------
__global__ void finalize_kernel(const float* __restrict__ e, float* __restrict__ out) {
    const size_t OFF = (size_t)B_ROWS * D_DIM;
    int i = blockIdx.x * 256 + threadIdx.x;
    int k = i >> 8, d = i & 255;
    int kx = k >> 5, ky = k & 31;

    #define SVAL(j) (g_sumx[(j) * D_DIM + d] - (float)g_cnt[j] * e[(j) * D_DIM + d])

    float center = SVAL(k);
    float nbsum = 0.f;
    if (kx >= 1)  nbsum += SVAL(((kx - 1) << 5) | ky);
    if (kx == 31) nbsum += center;
    if (kx <= 30) nbsum += SVAL(((kx + 1) << 5) | ky);
    if (kx == 0)  nbsum += center;
    if (ky <= 30) nbsum += SVAL((kx << 5) | (ky + 1));
    if (ky == 0)  nbsum += center;
    if (ky >= 1)  nbsum += SVAL((kx << 5) | (ky - 1));
    if (ky == 31) nbsum += center;

    out[OFF + 2 + i] = e[i] + LR_F * center + 0.5f * LR_F * nbsum;
    if (i == 0) {
        out[OFF]     = (float)(g_commit / ((double)B_ROWS * (double)D_DIM));
        out[OFF + 1] = (float)(g_som / ((double)B_ROWS * 4.0 * (double)D_DIM));
    }
    #undef SVAL
}

// ---------------- launch ----------------
extern "C" void kernel_launch(void* const* d_in, const int* in_sizes, int n_in,
                              void* d_out, int out_size) {
    const float* x = (const float*)d_in[0];
    const float* e = (const float*)d_in[1];
    float* out = (float*)d_out;

    cudaFuncSetAttribute(gemm_argmin_kernel,
                         cudaFuncAttributeMaxDynamicSharedMemorySize, SMEMD);

    prep_kernel<<<K_CL, 256>>>(e);
    convx_kernel<<<B_ROWS * D_DIM / 4 / 256, 256>>>(x);
    dim3 ggrid(NT, B_ROWS / TM);
    gemm_argmin_kernel<<<ggrid, 256, SMEMD>>>();
    select_kernel<<<B_ROWS / 32, 256>>>(x, e);
    phaseb_kernel<<<B_ROWS / 8, 256>>>(x, e, out);
    finalize_kernel<<<K_CL * D_DIM / 256, 256>>>(e, out);
}

// round 17
// speedup vs baseline: 1.4448x; 1.0793x over previous
#include <cuda_runtime.h>
#include <cuda_fp16.h>
#include <float.h>
#include <stdint.h>

#define B_ROWS 65536
#define K_CL   1024
#define D_DIM  256
#define LR_F   0.05f

#define TM     128        // CTA M tile
#define TN     128        // CTA N tile
#define NT     (K_CL / TN)   // 8 N-tiles
#define KC     64         // K per chunk (halfs)
#define NCHUNK (D_DIM / KC)  // 4
#define ROWB   144        // 64 halfs = 128B payload -> 144B padded row (16B aligned)
#define ATILE  (TM * ROWB)          // 18432 B
#define SMEMD  (4 * ATILE)          // A0,A1,B0,B1 = 73728 B

// ---------------- device scratch ----------------
__device__ __align__(16) float g_sumx[K_CL * D_DIM];   // per-cluster sum of x
__device__ int     g_cnt[K_CL];            // per-cluster row count
__device__ float   g_c[K_CL];              // ||e_k||^2
__device__ __align__(16) float g_f[K_CL * D_DIM];      // sum of 4 neighbor e-rows
__device__ float   g_g[K_CL];              // sum of 4 neighbor ||e||^2
__device__ double  g_commit;
__device__ double  g_som;
__device__ __half  g_xh[B_ROWS * D_DIM];
__device__ __half  g_eh[K_CL * D_DIM];
__device__ float4  g_cand[(size_t)B_ROWS * NT];   // top-2 per (row, tile)

// ---------------- helpers ----------------
__device__ __forceinline__ uint32_t smem_u32(const void* p) {
    uint32_t a;
    asm("{ .reg .u64 t; cvta.to.shared.u64 t, %1; cvt.u32.u64 %0, t; }" : "=r"(a) : "l"(p));
    return a;
}
__device__ __forceinline__ void ldsm4(uint32_t* r, uint32_t addr) {
    asm volatile("ldmatrix.sync.aligned.m8n8.x4.shared.b16 {%0,%1,%2,%3}, [%4];"
        : "=r"(r[0]), "=r"(r[1]), "=r"(r[2]), "=r"(r[3]) : "r"(addr));
}
__device__ __forceinline__ void mma_f16(float* c, const uint32_t* a, const uint32_t* b) {
    asm volatile("mma.sync.aligned.m16n8k16.row.col.f32.f16.f16.f32 "
        "{%0,%1,%2,%3}, {%4,%5,%6,%7}, {%8,%9}, {%0,%1,%2,%3};"
        : "+f"(c[0]), "+f"(c[1]), "+f"(c[2]), "+f"(c[3])
        : "r"(a[0]), "r"(a[1]), "r"(a[2]), "r"(a[3]), "r"(b[0]), "r"(b[1]));
}
#define CP_ASYNC16(dst, src) \
    asm volatile("cp.async.cg.shared.global [%0], [%1], 16;" :: "r"(dst), "l"(src))
#define CP_COMMIT()  asm volatile("cp.async.commit_group;" ::: "memory")
#define CP_WAIT(n)   asm volatile("cp.async.wait_group %0;" :: "n"(n) : "memory")

__device__ __forceinline__ void red_v4(float* ptr, float a, float b, float c, float d) {
    asm volatile("{ .reg .u64 p; cvta.to.global.u64 p, %0;\n\t"
                 "red.global.add.v4.f32 [p], {%1, %2, %3, %4}; }"
                 :: "l"(ptr), "f"(a), "f"(b), "f"(c), "f"(d) : "memory");
}
__device__ __forceinline__ bool lessc(float a, int ka, float b, int kb) {
    return a < b || (a == b && ka < kb);
}
__device__ __forceinline__ void merge2(float& bv, int& bk, float& sv, int& sk,
                                       float v, int k) {
    if (lessc(v, k, bv, bk)) { sv = bv; sk = bk; bv = v; bk = k; }
    else if (lessc(v, k, sv, sk)) { sv = v; sk = k; }
}
__device__ __forceinline__ void nbr4(int n, int* nb) {
    int nx = n >> 5, ny = n & 31;
    nb[0] = (nx < 31 ? nx + 1 : nx) * 32 + ny;   // up
    nb[1] = (nx > 0  ? nx - 1 : nx) * 32 + ny;   // down
    nb[2] = nx * 32 + (ny > 0  ? ny - 1 : ny);   // left
    nb[3] = nx * 32 + (ny < 31 ? ny + 1 : ny);   // right
}

// ---------------- prep: zero sumx/cnt, c[k]=||e_k||^2, e -> fp16, F vector ----------
__global__ void prep_kernel(const float* __restrict__ e) {
    int k = blockIdx.x, t = threadIdx.x;
    int idx = k * D_DIM + t;
    g_sumx[idx] = 0.0f;
    float v = e[idx];
    g_eh[idx] = __float2half_rn(v);

    int nb[4]; nbr4(k, nb);
    g_f[idx] = e[nb[0] * D_DIM + t] + e[nb[1] * D_DIM + t]
             + e[nb[2] * D_DIM + t] + e[nb[3] * D_DIM + t];

    float sq = v * v;
    #pragma unroll
    for (int off = 16; off > 0; off >>= 1)
        sq += __shfl_down_sync(0xffffffffu, sq, off);
    __shared__ float ws[8];
    int lane = t & 31, wid = t >> 5;
    if (lane == 0) ws[wid] = sq;
    __syncthreads();
    if (t == 0) {
        float s = 0.f;
        #pragma unroll
        for (int i = 0; i < 8; i++) s += ws[i];
        g_c[k] = s;
        g_cnt[k] = 0;
        if (k == 0) { g_commit = 0.0; g_som = 0.0; }
    }
}

// ---------------- convert x to fp16 ; block 0 computes G[k] ----------------
__global__ void convx_kernel(const float* __restrict__ x) {
    int i = blockIdx.x * 256 + threadIdx.x;          // float4 index
    float4 v = ((const float4*)x)[i];
    __half2* xh2 = (__half2*)g_xh;
    xh2[i * 2]     = __halves2half2(__float2half_rn(v.x), __float2half_rn(v.y));
    xh2[i * 2 + 1] = __halves2half2(__float2half_rn(v.z), __float2half_rn(v.w));

    if (blockIdx.x == 0) {
        #pragma unroll
        for (int j = 0; j < 4; j++) {
            int k = threadIdx.x * 4 + j;
            int nb[4]; nbr4(k, nb);
            g_g[k] = g_c[nb[0]] + g_c[nb[1]] + g_c[nb[2]] + g_c[nb[3]];
        }
    }
}

// ---------------- mma.sync fp16 GEMM (cp.async staged) + top-2 argmin epilogue -------
// grid (NT, B_ROWS/TM) = (8, 512); 256 threads; warp grid 2(M) x 4(N), warp tile 64x32.
// ONE sync per chunk: wait -> sync -> issue-next -> mma.
__global__ __launch_bounds__(256, 2) void gemm_argmin_kernel() {
    extern __shared__ __align__(128) char dsm[];
    __shared__ float cs[TN];

    const int tid = threadIdx.x;
    const int lane = tid & 31, wid = tid >> 5;
    const int wr = wid >> 2, wc = wid & 3;
    const int nt = blockIdx.x, n0 = nt * TN;
    const int m0 = blockIdx.y * TM;
    const uint32_t sb = smem_u32(dsm);

    if (tid < TN) cs[tid] = g_c[n0 + tid];

    const uint32_t aoff = (uint32_t)((wr * 64 + (lane & 15)) * ROWB + (lane >> 4) * 16);
    const uint32_t boff = (uint32_t)((wc * 32 + (lane & 7) + ((lane & 16) ? 8 : 0)) * ROWB
                                     + ((lane & 8) ? 16 : 0));

    float c[4][4][4];
    #pragma unroll
    for (int mi = 0; mi < 4; mi++)
        #pragma unroll
        for (int g = 0; g < 4; g++)
            #pragma unroll
            for (int e2 = 0; e2 < 4; e2++) c[mi][g][e2] = 0.f;

    // prologue: stage chunk 0 into buf 0
    {
        #pragma unroll
        for (int i = 0; i < 4; i++) {
            int idx = i * 256 + tid;
            int row = idx >> 3, q = idx & 7;
            uint32_t so = (uint32_t)(row * ROWB + q * 16);
            CP_ASYNC16(sb + so, g_xh + (size_t)(m0 + row) * D_DIM + q * 8);
            CP_ASYNC16(sb + 2 * ATILE + so, g_eh + (size_t)(n0 + row) * D_DIM + q * 8);
        }
        CP_COMMIT();
    }

    for (int ck = 0; ck < NCHUNK; ck++) {
        const int buf = ck & 1;

        CP_WAIT(0);              // chunk ck resident
        __syncthreads();         // also: everyone past mma(ck-1) -> safe to overwrite

        if (ck < NCHUNK - 1) {
            const int nb = (ck + 1) & 1;
            const int d0 = (ck + 1) * KC;
            #pragma unroll
            for (int i = 0; i < 4; i++) {
                int idx = i * 256 + tid;
                int row = idx >> 3, q = idx & 7;
                uint32_t so = (uint32_t)(nb * ATILE + row * ROWB + q * 16);
                CP_ASYNC16(sb + so, g_xh + (size_t)(m0 + row) * D_DIM + d0 + q * 8);
                CP_ASYNC16(sb + 2 * ATILE + so,
                           g_eh + (size_t)(n0 + row) * D_DIM + d0 + q * 8);
            }
            CP_COMMIT();
        }

        const uint32_t aAdr = sb + buf * ATILE + aoff;
        const uint32_t bAdr = sb + 2 * ATILE + buf * ATILE + boff;
        #pragma unroll
        for (int kj = 0; kj < 4; kj++) {        // 4 x K16 per K64 chunk
            uint32_t af[4][4], bfr[2][4];
            #pragma unroll
            for (int mi = 0; mi < 4; mi++) ldsm4(af[mi], aAdr + mi * 16 * ROWB + kj * 32);
            #pragma unroll
            for (int gp = 0; gp < 2; gp++) ldsm4(bfr[gp], bAdr + gp * 16 * ROWB + kj * 32);
            #pragma unroll
            for (int mi = 0; mi < 4; mi++)
                #pragma unroll
                for (int g = 0; g < 4; g++)
                    mma_f16(c[mi][g], af[mi], &bfr[g >> 1][(g & 1) * 2]);
        }
    }

    // ---- epilogue: per-row top-2 over this CTA's 128 cols ----
    // red[] occupies buf0's A-tile region — disjoint from the final chunk's buffers
    // (buf1), so no extra sync needed before the writes below.
    float2* red = (float2*)dsm;

    #pragma unroll
    for (int mi = 0; mi < 4; mi++) {
        #pragma unroll
        for (int half = 0; half < 2; half++) {
            int rloc = wr * 64 + mi * 16 + (lane >> 2) + half * 8;
            float bv = FLT_MAX, sv = FLT_MAX;
            int bk = 0x7fffffff, sk = 0x7fffffff;
            #pragma unroll
            for (int g = 0; g < 4; g++) {
                #pragma unroll
                for (int e2 = 0; e2 < 2; e2++) {
                    int col = wc * 32 + g * 8 + (lane & 3) * 2 + e2;
                    float s = cs[col] - 2.0f * c[mi][g][half * 2 + e2];
                    merge2(bv, bk, sv, sk, s, n0 + col);
                }
            }
            #pragma unroll
            for (int off = 1; off <= 2; off <<= 1) {
                float obv = __shfl_xor_sync(0xffffffffu, bv, off);
                int   obk = __shfl_xor_sync(0xffffffffu, bk, off);
                float osv = __shfl_xor_sync(0xffffffffu, sv, off);
                int   osk = __shfl_xor_sync(0xffffffffu, sk, off);
                merge2(bv, bk, sv, sk, obv, obk);
                merge2(bv, bk, sv, sk, osv, osk);
            }
            if ((lane & 3) == 0) {
                red[(rloc * 4 + wc) * 2 + 0] = make_float2(bv, __int_as_float(bk));
                red[(rloc * 4 + wc) * 2 + 1] = make_float2(sv, __int_as_float(sk));
            }
        }
    }
    __syncthreads();

    if (tid < TM) {
        float bv = FLT_MAX, sv = FLT_MAX;
        int bk = 0x7fffffff, sk = 0x7fffffff;
        #pragma unroll
        for (int w = 0; w < 4; w++)
            #pragma unroll
            for (int p = 0; p < 2; p++) {
                float2 t = red[(tid * 4 + w) * 2 + p];
                merge2(bv, bk, sv, sk, t.x, __float_as_int(t.y));
            }
        g_cand[(size_t)(m0 + tid) * NT + nt] =
            make_float4(bv, __int_as_float(bk), sv, __int_as_float(sk));
    }
}

// ---------------- fused select + phase B: warp per row ------------------------------
// Lanes 0-7 load candidates; ALL butterflies are full-warp (off 1..16) so bv/bk/cnt
// are warp-uniform -> the cnt>1 branch is uniform -> all shfls are full-warp legal.
// Rescore arithmetic per (b,k) bit-matches the passing R14 select.
#define MARGIN 0.05f
__global__ void spb_kernel(const float* __restrict__ x, const float* __restrict__ e,
                           float* __restrict__ out) {
    const int warp = threadIdx.x >> 5;
    const int lane = threadIdx.x & 31;
    const int b = blockIdx.x * 8 + warp;

    // ---- select part ----
    float v0 = FLT_MAX, v1 = FLT_MAX;
    int k0 = 0x7fffffff, k1 = 0x7fffffff;
    if (lane < 8) {
        float4 c0 = g_cand[(size_t)b * NT + lane];
        v0 = c0.x; k0 = __float_as_int(c0.y);
        v1 = c0.z; k1 = __float_as_int(c0.w);
    }
    float bv = v0; int bk = k0;
    if (lessc(v1, k1, bv, bk)) { bv = v1; bk = k1; }
    #pragma unroll
    for (int off = 1; off < 32; off <<= 1) {        // FULL-warp butterfly
        float ov = __shfl_xor_sync(0xffffffffu, bv, off);
        int   ok = __shfl_xor_sync(0xffffffffu, bk, off);
        if (lessc(ov, ok, bv, bk)) { bv = ov; bk = ok; }
    }

    // margin count: neutral lanes' FLT_MAX fails the test vs the (real) warp min
    int cnt = (v0 <= bv + MARGIN ? 1 : 0) + (v1 <= bv + MARGIN ? 1 : 0);
    #pragma unroll
    for (int off = 1; off < 32; off <<= 1)          // FULL-warp butterfly
        cnt += __shfl_xor_sync(0xffffffffu, cnt, off);

    if (cnt > 1) {                                   // warp-uniform branch
        float bs = FLT_MAX; int bki = 0x7fffffff;
        const float* xr = x + (size_t)b * D_DIM;
        float vv[2] = {v0, v1};
        int   kv[2] = {k0, k1};
        #pragma unroll
        for (int p = 0; p < 2; p++) {
            if (vv[p] > bv + MARGIN) continue;
            int k = kv[p];
            if ((unsigned)k >= (unsigned)K_CL) continue;   // sentinel guard
            float dot = 0.0f;
            const float* er = e + (size_t)k * D_DIM;
            #pragma unroll 8
            for (int d = 0; d < D_DIM; d++) dot = fmaf(xr[d], er[d], dot);
            float s = g_c[k] - 2.0f * dot;
            if (lessc(s, k, bs, bki)) { bs = s; bki = k; }
        }
        #pragma unroll
        for (int off = 1; off < 32; off <<= 1) {    // FULL-warp butterfly
            float os = __shfl_xor_sync(0xffffffffu, bs, off);
            int   ok = __shfl_xor_sync(0xffffffffu, bki, off);
            if (lessc(os, ok, bs, bki)) { bs = os; bki = ok; }
        }
        if ((unsigned)bki < (unsigned)K_CL) bk = bki;
    }

    const int n = bk;                                // warp-uniform
    if (lane == 0) atomicAdd(&g_cnt[n], 1);

    // ---- phaseb part (all 32 lanes) ----
    const float4* xr4 = (const float4*)(x + (size_t)b * D_DIM);
    const float4* zr  = (const float4*)(e + (size_t)n * D_DIM);
    const float4* fr  = (const float4*)(g_f + (size_t)n * D_DIM);
    float4* zout = (float4*)out + (size_t)b * (D_DIM / 4);

    float commit = 0.f, som = 0.f;

    #pragma unroll
    for (int it = 0; it < 2; it++) {
        int q = lane + it * 32;
        float4 xv = xr4[q];
        float4 zq = zr[q];
        float4 fv = fr[q];
        zout[q] = zq;
        float4 dw = make_float4(xv.x - zq.x, xv.y - zq.y, xv.z - zq.z, xv.w - zq.w);
        commit += dw.x * dw.x + dw.y * dw.y + dw.z * dw.z + dw.w * dw.w;

        float xx = xv.x * xv.x + xv.y * xv.y + xv.z * xv.z + xv.w * xv.w;
        float xf = xv.x * fv.x + xv.y * fv.y + xv.z * fv.z + xv.w * fv.w;
        som += 4.0f * xx - 2.0f * xf;

        red_v4(&g_sumx[n * D_DIM + q * 4], xv.x, xv.y, xv.z, xv.w);
    }

    #pragma unroll
    for (int off = 16; off > 0; off >>= 1) {
        commit += __shfl_down_sync(0xffffffffu, commit, off);
        som    += __shfl_down_sync(0xffffffffu, som, off);
    }
    if (lane == 0) {
        som += g_g[n];
        atomicAdd(&g_commit, (double)commit);
        atomicAdd(&g_som, (double)som);
    }
}

// ---------------- finalize: reconstruct all 5 segment terms from S ----------------
__global__ void finalize_kernel(const float* __restrict__ e, float* __restrict__ out) {
    const size_t OFF = (size_t)B_ROWS * D_DIM;
    int i = blockIdx.x * 256 + threadIdx.x;
    int k = i >> 8, d = i & 255;
    int kx = k >> 5, ky = k & 31;

    #define SVAL(j) (g_sumx[(j) * D_DIM + d] - (float)g_cnt[j] * e[(j) * D_DIM + d])

    float center = SVAL(k);
    float nbsum = 0.f;
    if (kx >= 1)  nbsum += SVAL(((kx - 1) << 5) | ky);
    if (kx == 31) nbsum += center;
    if (kx <= 30) nbsum += SVAL(((kx + 1) << 5) | ky);
    if (kx == 0)  nbsum += center;
    if (ky <= 30) nbsum += SVAL((kx << 5) | (ky + 1));
    if (ky == 0)  nbsum += center;
    if (ky >= 1)  nbsum += SVAL((kx << 5) | (ky - 1));
    if (ky == 31) nbsum += center;

    out[OFF + 2 + i] = e[i] + LR_F * center + 0.5f * LR_F * nbsum;
    if (i == 0) {
        out[OFF]     = (float)(g_commit / ((double)B_ROWS * (double)D_DIM));
        out[OFF + 1] = (float)(g_som / ((double)B_ROWS * 4.0 * (double)D_DIM));
    }
    #undef SVAL
}

// ---------------- launch ----------------
extern "C" void kernel_launch(void* const* d_in, const int* in_sizes, int n_in,
                              void* d_out, int out_size) {
    const float* x = (const float*)d_in[0];
    const float* e = (const float*)d_in[1];
    float* out = (float*)d_out;

    cudaFuncSetAttribute(gemm_argmin_kernel,
                         cudaFuncAttributeMaxDynamicSharedMemorySize, SMEMD);

    prep_kernel<<<K_CL, 256>>>(e);
    convx_kernel<<<B_ROWS * D_DIM / 4 / 256, 256>>>(x);
    dim3 ggrid(NT, B_ROWS / TM);
    gemm_argmin_kernel<<<ggrid, 256, SMEMD>>>();
    spb_kernel<<<B_ROWS / 8, 256>>>(x, e, out);
    finalize_kernel<<<K_CL * D_DIM / 256, 256>>>(e, out);
}